// round 7
// baseline (speedup 1.0000x reference)
#include <cuda_runtime.h>
#include <cstdint>

// RandomShiftsAug == integer shifted gather with edge clamp:
//   out[n,c,j,i] = x[n,c, clamp(j+sy-4,0,83), clamp(i+sx-4,0,83)]
//
// R5 structure (lane-contiguous scalar, 4x7 batched loads, occ 87%) + R6 L2
// residency plan, with the ptxas-legal encoding: scalar loads carry an
// evict_last policy via createpolicy + ld.global.nc.L2::cache_hint (direct
// .L2::evict_last is vector-only on sm_103a). Stores stay st.global.cs so the
// 130MB output stream evicts itself rather than the L2-resident input.

#define N_   512
#define C_   9
#define H_   84
#define W_   84
#define PAD_ 4

#define SLICE    (H_ * W_)     // 7056
#define THREADS  252           // 3 rows x 84 cols
#define CHUNK    7
#define NCHUNK   4             // 28 rows per thread

__device__ __forceinline__ uint64_t make_evict_last_policy() {
    uint64_t pol;
    asm("createpolicy.fractional.L2::evict_last.b64 %0, 1.0;" : "=l"(pol));
    return pol;
}

__device__ __forceinline__ float ldg_hint(const float* p, uint64_t pol) {
    float v;
    asm volatile("ld.global.nc.L2::cache_hint.f32 %0, [%1], %2;"
                 : "=f"(v) : "l"(p), "l"(pol));
    return v;
}

__device__ __forceinline__ void stg_streaming(float* p, float v) {
    asm volatile("st.global.cs.f32 [%0], %1;" :: "l"(p), "f"(v) : "memory");
}

__global__ __launch_bounds__(THREADS, 8) void random_shift_l2_kernel(
    const float* __restrict__ x,
    const int*   __restrict__ shift,
    float*       __restrict__ out)
{
    const int nc  = blockIdx.x;          // (n*C + c)
    const int n   = nc / C_;
    const int tid = threadIdx.x;

    const int i  = tid % W_;             // column, 0..83
    const int j0 = tid / W_;             // starting row, 0..2

    const int sx = __ldg(&shift[2 * n + 0]) - PAD_;   // [-4, 4]
    const int sy = __ldg(&shift[2 * n + 1]) - PAD_;

    const int srcx = min(max(i + sx, 0), W_ - 1);     // column clamp, hoisted

    const uint64_t pol = make_evict_last_policy();

    const float* __restrict__ src = x   + (long)nc * SLICE + srcx;
    float*       __restrict__ dst = out + (long)nc * SLICE + i;

    #pragma unroll
    for (int c = 0; c < NCHUNK; c++) {
        float v[CHUNK];
        #pragma unroll
        for (int k = 0; k < CHUNK; k++) {
            int j = j0 + 3 * (c * CHUNK + k);         // output row
            int srcy = min(max(j + sy, 0), H_ - 1);
            v[k] = ldg_hint(src + srcy * W_, pol);
        }
        #pragma unroll
        for (int k = 0; k < CHUNK; k++) {
            int j = j0 + 3 * (c * CHUNK + k);
            stg_streaming(dst + j * W_, v[k]);
        }
    }
}

extern "C" void kernel_launch(void* const* d_in, const int* in_sizes, int n_in,
                              void* d_out, int out_size)
{
    const float* x     = (const float*)d_in[0];
    const int*   shift = (const int*)  d_in[1];
    float* out = (float*)d_out;

    random_shift_l2_kernel<<<N_ * C_, THREADS>>>(x, shift, out);
}